// round 14
// baseline (speedup 1.0000x reference)
#include <cuda_runtime.h>

// out[row, e] = cos(x[row, 1]) * W_dec[e] + b_dec[e]
// x: (32768, 1024) fp32 ; W_dec,b_dec: (1024,) ; out: (32768, 1024)
// R13 FINAL: byte-for-byte resubmission of the R4 champion (23.42us, best
// of 12 rounds). Pinned at the DRAM write ceiling (~5.7 TB/s effective):
// store-issue and LTS both have ~2x headroom; all alternative store
// mechanisms (v8, TMA bulk, wb, evict_last pinning, persistent grid,
// barrier-free broadcast, straight-line burst) measured and rejected.

#define EMBED 1024
#define VEC 4                    // float4
#define THREADS (EMBED / VEC)    // 256 threads cover one row per store round
#define ROWS_PER_BLOCK 4

__global__ __launch_bounds__(THREADS)
void vql_kernel(const float* __restrict__ x,
                const float* __restrict__ W,
                const float* __restrict__ b,
                float* __restrict__ out,
                int n_rows)
{
    __shared__ float s_cos[ROWS_PER_BLOCK];

    const int tid  = threadIdx.x;
    const int row0 = blockIdx.x * ROWS_PER_BLOCK;

    // Threads 0..3 compute cos(x[row,1]) for this block's rows.
    if (tid < ROWS_PER_BLOCK) {
        int r = row0 + tid;
        float v = 0.0f;
        if (r < n_rows)
            v = __ldg(&x[(size_t)r * EMBED + 1]);
        s_cos[tid] = cosf(v);
    }
    __syncthreads();

    // W/b chunk for this thread, register-resident across all 4 rows.
    const float4 w4 = __ldg(reinterpret_cast<const float4*>(W) + tid);
    const float4 b4 = __ldg(reinterpret_cast<const float4*>(b) + tid);

    float4* o = reinterpret_cast<float4*>(out) + (size_t)row0 * (EMBED / VEC) + tid;

    #pragma unroll
    for (int i = 0; i < ROWS_PER_BLOCK; ++i) {
        if (row0 + i >= n_rows) break;
        const float c = s_cos[i];
        float4 v;
        v.x = fmaf(c, w4.x, b4.x);
        v.y = fmaf(c, w4.y, b4.y);
        v.z = fmaf(c, w4.z, b4.z);
        v.w = fmaf(c, w4.w, b4.w);
        // Streaming store: output is write-once, evict-first in L2.
        __stcs(o + (size_t)i * (EMBED / VEC), v);
    }
}

extern "C" void kernel_launch(void* const* d_in, const int* in_sizes, int n_in,
                              void* d_out, int out_size)
{
    const float* x = (const float*)d_in[0];   // (32768, 1024)
    const float* W = (const float*)d_in[1];   // 1024 floats
    const float* b = (const float*)d_in[2];   // 1024 floats
    float* out = (float*)d_out;

    const int n_rows = in_sizes[0] / EMBED;                            // 32768
    const int grid = (n_rows + ROWS_PER_BLOCK - 1) / ROWS_PER_BLOCK;   // 8192

    vql_kernel<<<grid, THREADS>>>(x, W, b, out, n_rows);
}